// round 1
// baseline (speedup 1.0000x reference)
#include <cuda_runtime.h>
#include <cstdint>

// ---------------------------------------------------------------------------
// GCN: out = SpMM(relu(SpMM(X@W1+b1)) @ W2 + b2)
// Inputs (metadata order): X[100000,256] f32, W1[256,128] f32, b1[128] f32,
//                          W2[128,128] f32, b2[128] f32, vals[E] f32,
//                          row[E] i32, col[E] i32.  Output: [100000,128] f32.
// ---------------------------------------------------------------------------

#define MAX_NODES 100000
#define FEAT 128

// Scratch (static device globals: allocation-free per harness rules)
__device__ float g_H1[(size_t)MAX_NODES * FEAT];  // X@W1+b1
__device__ float g_S1[(size_t)MAX_NODES * FEAT];  // SpMM1 accumulator (pre-relu)
__device__ float g_H2[(size_t)MAX_NODES * FEAT];  // relu(S1)@W2+b2

// ---------------------------------------------------------------------------
// Zero two buffers (SpMM accumulators need zero-init; d_out is poisoned)
// ---------------------------------------------------------------------------
__global__ void zero2_kernel(float4* __restrict__ a, float4* __restrict__ b, int n4)
{
    int i = blockIdx.x * blockDim.x + threadIdx.x;
    int stride = gridDim.x * blockDim.x;
    float4 z = make_float4(0.f, 0.f, 0.f, 0.f);
    for (int j = i; j < n4; j += stride) {
        a[j] = z;
        b[j] = z;
    }
}

// ---------------------------------------------------------------------------
// GEMM + bias (+ optional ReLU applied to A on load):
//   C[M, 128] = act(A)[M, K] @ W[K, 128] + bias
// Block: 256 threads, BM=64 rows, BK=32. Each thread: 8 rows x 4 cols.
// A-reads from smem are warp-broadcast (all lanes same addr); W-reads are
// conflict-free LDS.128 -> loop is FFMA-pipe bound.
// ---------------------------------------------------------------------------
template <int K, bool RELU>
__global__ __launch_bounds__(256) void gemm_bias_kernel(
    const float* __restrict__ A, const float* __restrict__ W,
    const float* __restrict__ bias, float* __restrict__ C, int M)
{
    constexpr int BM = 64, BK = 32, N = 128;
    __shared__ float As[BM][BK];   // 8 KB
    __shared__ float Ws[BK][N];    // 16 KB

    const int tid = threadIdx.x;
    const int tx  = tid & 31;      // column group: cols [4*tx, 4*tx+3]
    const int ty  = tid >> 5;      // row base: rows ty + 8*i
    const int m0  = blockIdx.x * BM;

    float4 acc[8];
#pragma unroll
    for (int i = 0; i < 8; i++) acc[i] = make_float4(0.f, 0.f, 0.f, 0.f);

    for (int k0 = 0; k0 < K; k0 += BK) {
        // Load A tile [64 x 32]: 512 float4, 2 per thread (coalesced 128B rows)
#pragma unroll
        for (int i = 0; i < 2; i++) {
            int idx = tid + i * 256;
            int rr = idx >> 3;            // row within tile
            int cc = (idx & 7) << 2;      // float col within tile
            int gr = m0 + rr;
            float4 v = make_float4(0.f, 0.f, 0.f, 0.f);
            if (gr < M)
                v = *(const float4*)(A + (size_t)gr * K + k0 + cc);
            if (RELU) {
                v.x = fmaxf(v.x, 0.f); v.y = fmaxf(v.y, 0.f);
                v.z = fmaxf(v.z, 0.f); v.w = fmaxf(v.w, 0.f);
            }
            *(float4*)(&As[rr][cc]) = v;
        }
        // Load W tile [32 x 128]: 1024 float4, 4 per thread (coalesced)
#pragma unroll
        for (int i = 0; i < 4; i++) {
            int idx = tid + i * 256;
            int rr = idx >> 5;
            int cc = (idx & 31) << 2;
            *(float4*)(&Ws[rr][cc]) = *(const float4*)(W + (size_t)(k0 + rr) * N + cc);
        }
        __syncthreads();

#pragma unroll
        for (int kk = 0; kk < BK; kk++) {
            float4 w = *(const float4*)(&Ws[kk][tx << 2]);
#pragma unroll
            for (int i = 0; i < 8; i++) {
                float a = As[ty + (i << 3)][kk];   // warp-broadcast LDS
                acc[i].x += a * w.x;
                acc[i].y += a * w.y;
                acc[i].z += a * w.z;
                acc[i].w += a * w.w;
            }
        }
        __syncthreads();
    }

    float4 b = *(const float4*)(bias + (tx << 2));
#pragma unroll
    for (int i = 0; i < 8; i++) {
        int gr = m0 + ty + (i << 3);
        if (gr < M) {
            float4 o = make_float4(acc[i].x + b.x, acc[i].y + b.y,
                                   acc[i].z + b.z, acc[i].w + b.w);
            *(float4*)(C + (size_t)gr * N + (tx << 2)) = o;
        }
    }
}

// ---------------------------------------------------------------------------
// COO SpMM: out[row[e]] += vals[e] * H[col[e]]  (feature dim = 128)
// One warp per edge. Lane l handles floats [4l, 4l+3]:
//   - 512B fully-coalesced gather of H[col[e]]
//   - vector reduction red.global.add.v4.f32 (sm_90+) into out[row[e]]
// Both the 51.2MB gather table and accumulator fit in L2 together.
// ---------------------------------------------------------------------------
__global__ __launch_bounds__(256) void spmm_kernel(
    const int* __restrict__ row, const int* __restrict__ col,
    const float* __restrict__ vals, const float* __restrict__ H,
    float* __restrict__ out, int nE)
{
    int e    = (blockIdx.x * 256 + threadIdx.x) >> 5;
    int lane = threadIdx.x & 31;
    if (e >= nE) return;

    int   r = row[e];      // warp-uniform loads: single sector per warp
    int   c = col[e];
    float v = vals[e];

    float4 h = *(const float4*)(H + (size_t)c * FEAT + (lane << 2));
    float4 p = make_float4(v * h.x, v * h.y, v * h.z, v * h.w);

    float* dst = out + (size_t)r * FEAT + (lane << 2);
    asm volatile("red.global.add.v4.f32 [%0], {%1, %2, %3, %4};"
                 :: "l"(dst), "f"(p.x), "f"(p.y), "f"(p.z), "f"(p.w)
                 : "memory");
}

// ---------------------------------------------------------------------------
// Launch
// ---------------------------------------------------------------------------
extern "C" void kernel_launch(void* const* d_in, const int* in_sizes, int n_in,
                              void* d_out, int out_size)
{
    const float* X    = (const float*)d_in[0];
    const float* W1   = (const float*)d_in[1];
    const float* b1   = (const float*)d_in[2];
    const float* W2   = (const float*)d_in[3];
    const float* b2   = (const float*)d_in[4];
    const float* vals = (const float*)d_in[5];
    const int*   row  = (const int*)d_in[6];
    const int*   col  = (const int*)d_in[7];

    const int M  = in_sizes[0] / 256;   // 100000
    const int nE = in_sizes[5];         // 1600000

    float *H1, *S1, *H2;
    cudaGetSymbolAddress((void**)&H1, g_H1);
    cudaGetSymbolAddress((void**)&S1, g_S1);
    cudaGetSymbolAddress((void**)&H2, g_H2);
    float* out = (float*)d_out;

    const int n4 = (M * FEAT) / 4;
    zero2_kernel<<<2048, 256>>>((float4*)S1, (float4*)out, n4);

    const int gemm_blocks = (M + 63) / 64;
    gemm_bias_kernel<256, false><<<gemm_blocks, 256>>>(X, W1, b1, H1, M);

    const int spmm_blocks = (nE + 7) / 8;  // 8 warps (edges) per block
    spmm_kernel<<<spmm_blocks, 256>>>(row, col, vals, H1, S1, nE);

    gemm_bias_kernel<128, true><<<gemm_blocks, 256>>>(S1, W2, b2, H2, M);

    spmm_kernel<<<spmm_blocks, 256>>>(row, col, vals, H2, out, nE);
}

// round 2
// speedup vs baseline: 1.5089x; 1.5089x over previous
#include <cuda_runtime.h>
#include <cstdint>

// ---------------------------------------------------------------------------
// GCN: out = SpMM(relu(SpMM(X@W1+b1)) @ W2 + b2)
// R2: atomic-free SpMM via per-launch row-sort (hist/scan/scatter -> CSR),
//     register-blocked 128x128x16 SGEMM (8x8 acc/thread).
// ---------------------------------------------------------------------------

#define MAX_NODES 100000
#define MAX_EDGES 1600000
#define FEAT 128
#define SCAN_B 512          // elements per scan block
#define SCAN_NB ((MAX_NODES + SCAN_B - 1) / SCAN_B)   // 196

// Scratch
__device__ float g_H [(size_t)MAX_NODES * FEAT];   // GEMM output (H1, reused as H2)
__device__ float g_S1[(size_t)MAX_NODES * FEAT];   // SpMM1 output (pre-relu)
__device__ int   g_cnt[MAX_NODES];
__device__ int   g_row_start[MAX_NODES + 1];
__device__ int   g_row_next[MAX_NODES];
__device__ int   g_partials[SCAN_NB];
__device__ int   g_scol[MAX_EDGES];
__device__ float g_sval[MAX_EDGES];

// ---------------------------------------------------------------------------
// Sorting pipeline: zero counters -> histogram -> 3-phase exclusive scan ->
// scatter permutation. Deterministic work every call; per-row edge order may
// vary (atomic ticket) which only permutes fp add order (tolerance-checked).
// ---------------------------------------------------------------------------
__global__ void zero_cnt_kernel(int* __restrict__ cnt, int n)
{
    int i = blockIdx.x * blockDim.x + threadIdx.x;
    if (i < n) cnt[i] = 0;
}

__global__ void hist_kernel(const int* __restrict__ row, int nE, int* __restrict__ cnt)
{
    int i = blockIdx.x * blockDim.x + threadIdx.x;
    if (i < nE) atomicAdd(&cnt[row[i]], 1);
}

__global__ void scan1_kernel(const int* __restrict__ cnt, int* __restrict__ partials, int n)
{
    __shared__ int sh[SCAN_B];
    int i = blockIdx.x * SCAN_B + threadIdx.x;
    sh[threadIdx.x] = (i < n) ? cnt[i] : 0;
    __syncthreads();
#pragma unroll
    for (int off = SCAN_B / 2; off > 0; off >>= 1) {
        if (threadIdx.x < off) sh[threadIdx.x] += sh[threadIdx.x + off];
        __syncthreads();
    }
    if (threadIdx.x == 0) partials[blockIdx.x] = sh[0];
}

// Single block: exclusive-scan the <=256 block partials; write total to row_start[n].
__global__ void scan2_kernel(int* __restrict__ partials, int nb,
                             int* __restrict__ row_start, int n)
{
    __shared__ int sh[256];
    int tid = threadIdx.x;
    int v = (tid < nb) ? partials[tid] : 0;
    sh[tid] = v;
    __syncthreads();
#pragma unroll
    for (int off = 1; off < 256; off <<= 1) {
        int t = (tid >= off) ? sh[tid - off] : 0;
        __syncthreads();
        sh[tid] += t;
        __syncthreads();
    }
    if (tid < nb) partials[tid] = sh[tid] - v;        // exclusive
    if (tid == 255) row_start[n] = sh[255];           // grand total
}

__global__ void scan3_kernel(const int* __restrict__ cnt, const int* __restrict__ partials,
                             int* __restrict__ row_start, int* __restrict__ row_next, int n)
{
    __shared__ int sh[SCAN_B];
    int tid = threadIdx.x;
    int i = blockIdx.x * SCAN_B + tid;
    int v = (i < n) ? cnt[i] : 0;
    sh[tid] = v;
    __syncthreads();
#pragma unroll
    for (int off = 1; off < SCAN_B; off <<= 1) {
        int t = (tid >= off) ? sh[tid - off] : 0;
        __syncthreads();
        sh[tid] += t;
        __syncthreads();
    }
    if (i < n) {
        int excl = sh[tid] - v + partials[blockIdx.x];
        row_start[i] = excl;
        row_next[i]  = excl;
    }
}

__global__ void scatter_kernel(const int* __restrict__ row, const int* __restrict__ col,
                               const float* __restrict__ vals, int nE,
                               int* __restrict__ row_next,
                               int* __restrict__ scol, float* __restrict__ sval)
{
    int i = blockIdx.x * blockDim.x + threadIdx.x;
    if (i < nE) {
        int r = row[i];
        int p = atomicAdd(&row_next[r], 1);
        scol[p] = col[i];
        sval[p] = vals[i];
    }
}

// ---------------------------------------------------------------------------
// Register-blocked SGEMM + bias (+ReLU on A): C[M,128] = act(A)[M,K] @ W + b
// BM=128, BN=128, BK=16; 256 threads, 8x8 acc/thread.
// A stored transposed in smem -> frag loads are LDS.128.
// ---------------------------------------------------------------------------
template <int K, bool RELU>
__global__ __launch_bounds__(256) void gemm_bias_kernel(
    const float* __restrict__ A, const float* __restrict__ W,
    const float* __restrict__ bias, float* __restrict__ C, int M)
{
    constexpr int BM = 128, BK = 16, N = 128;
    __shared__ float As[BK][BM + 4];   // transposed A tile, padded
    __shared__ float Ws[BK][N];

    const int tid = threadIdx.x;
    const int tn  = tid & 15;    // col group: cols [8*tn, 8*tn+7]
    const int tm  = tid >> 4;    // row group: rows [8*tm, 8*tm+7]
    const int m0  = blockIdx.x * BM;

    float acc[8][8];
#pragma unroll
    for (int i = 0; i < 8; i++)
#pragma unroll
        for (int j = 0; j < 8; j++) acc[i][j] = 0.f;

    for (int k0 = 0; k0 < K; k0 += BK) {
        // A tile [128 x 16] -> transposed store. 512 float4, 2/thread.
#pragma unroll
        for (int i = 0; i < 2; i++) {
            int idx = tid + i * 256;
            int rr  = idx >> 2;          // 0..127
            int cc  = (idx & 3) << 2;    // 0,4,8,12
            float4 v = make_float4(0.f, 0.f, 0.f, 0.f);
            int gr = m0 + rr;
            if (gr < M)
                v = *(const float4*)(A + (size_t)gr * K + k0 + cc);
            if (RELU) {
                v.x = fmaxf(v.x, 0.f); v.y = fmaxf(v.y, 0.f);
                v.z = fmaxf(v.z, 0.f); v.w = fmaxf(v.w, 0.f);
            }
            As[cc + 0][rr] = v.x;
            As[cc + 1][rr] = v.y;
            As[cc + 2][rr] = v.z;
            As[cc + 3][rr] = v.w;
        }
        // W tile [16 x 128]: 512 float4, 2/thread, coalesced.
#pragma unroll
        for (int i = 0; i < 2; i++) {
            int idx = tid + i * 256;
            int rr  = idx >> 5;
            int cc  = (idx & 31) << 2;
            *(float4*)(&Ws[rr][cc]) = *(const float4*)(W + (size_t)(k0 + rr) * N + cc);
        }
        __syncthreads();

#pragma unroll
        for (int kk = 0; kk < BK; kk++) {
            float a[8], b[8];
            *(float4*)&a[0] = *(const float4*)(&As[kk][tm * 8]);
            *(float4*)&a[4] = *(const float4*)(&As[kk][tm * 8 + 4]);
            *(float4*)&b[0] = *(const float4*)(&Ws[kk][tn * 8]);
            *(float4*)&b[4] = *(const float4*)(&Ws[kk][tn * 8 + 4]);
#pragma unroll
            for (int i = 0; i < 8; i++)
#pragma unroll
                for (int j = 0; j < 8; j++)
                    acc[i][j] += a[i] * b[j];
        }
        __syncthreads();
    }

    float bb[8];
    *(float4*)&bb[0] = *(const float4*)(bias + tn * 8);
    *(float4*)&bb[4] = *(const float4*)(bias + tn * 8 + 4);
#pragma unroll
    for (int i = 0; i < 8; i++) {
        int gr = m0 + tm * 8 + i;
        if (gr < M) {
            float4 o0 = make_float4(acc[i][0] + bb[0], acc[i][1] + bb[1],
                                    acc[i][2] + bb[2], acc[i][3] + bb[3]);
            float4 o1 = make_float4(acc[i][4] + bb[4], acc[i][5] + bb[5],
                                    acc[i][6] + bb[6], acc[i][7] + bb[7]);
            float* cp = C + (size_t)gr * N + tn * 8;
            *(float4*)(cp)     = o0;
            *(float4*)(cp + 4) = o1;
        }
    }
}

// ---------------------------------------------------------------------------
// CSR SpMM, atomic-free: warp per row, lane l owns floats [4l,4l+3].
// out[r] = sum_{i in [row_start[r], row_start[r+1])} sval[i] * H[scol[i]]
// Every row is written -> no zero-init needed anywhere.
// ---------------------------------------------------------------------------
__global__ __launch_bounds__(256) void spmm_csr_kernel(
    const int* __restrict__ row_start,
    const int* __restrict__ scol, const float* __restrict__ sval,
    const float* __restrict__ H, float* __restrict__ out, int n)
{
    int r    = blockIdx.x * 8 + (threadIdx.x >> 5);
    int lane = threadIdx.x & 31;
    if (r >= n) return;

    int s = row_start[r];
    int e = row_start[r + 1];

    float4 acc = make_float4(0.f, 0.f, 0.f, 0.f);
    int i = s;
    for (; i + 2 <= e; i += 2) {                 // 2-deep MLP
        int   c0 = scol[i],     c1 = scol[i + 1];
        float v0 = sval[i],     v1 = sval[i + 1];
        float4 h0 = *(const float4*)(H + (size_t)c0 * FEAT + (lane << 2));
        float4 h1 = *(const float4*)(H + (size_t)c1 * FEAT + (lane << 2));
        acc.x += v0 * h0.x + v1 * h1.x;
        acc.y += v0 * h0.y + v1 * h1.y;
        acc.z += v0 * h0.z + v1 * h1.z;
        acc.w += v0 * h0.w + v1 * h1.w;
    }
    if (i < e) {
        int   c = scol[i];
        float v = sval[i];
        float4 h = *(const float4*)(H + (size_t)c * FEAT + (lane << 2));
        acc.x += v * h.x; acc.y += v * h.y; acc.z += v * h.z; acc.w += v * h.w;
    }
    *(float4*)(out + (size_t)r * FEAT + (lane << 2)) = acc;
}

// ---------------------------------------------------------------------------
extern "C" void kernel_launch(void* const* d_in, const int* in_sizes, int n_in,
                              void* d_out, int out_size)
{
    const float* X    = (const float*)d_in[0];
    const float* W1   = (const float*)d_in[1];
    const float* b1   = (const float*)d_in[2];
    const float* W2   = (const float*)d_in[3];
    const float* b2   = (const float*)d_in[4];
    const float* vals = (const float*)d_in[5];
    const int*   row  = (const int*)d_in[6];
    const int*   col  = (const int*)d_in[7];

    const int M  = in_sizes[0] / 256;   // 100000
    const int nE = in_sizes[5];         // 1600000

    float *H, *S1;
    int *cnt, *row_start, *row_next, *partials, *scol;
    float *sval;
    cudaGetSymbolAddress((void**)&H,         g_H);
    cudaGetSymbolAddress((void**)&S1,        g_S1);
    cudaGetSymbolAddress((void**)&cnt,       g_cnt);
    cudaGetSymbolAddress((void**)&row_start, g_row_start);
    cudaGetSymbolAddress((void**)&row_next,  g_row_next);
    cudaGetSymbolAddress((void**)&partials,  g_partials);
    cudaGetSymbolAddress((void**)&scol,      g_scol);
    cudaGetSymbolAddress((void**)&sval,      g_sval);
    float* out = (float*)d_out;

    const int nb = (M + SCAN_B - 1) / SCAN_B;          // 196

    // --- sort edges by row (CSR build) ---
    zero_cnt_kernel<<<(M + 255) / 256, 256>>>(cnt, M);
    hist_kernel<<<(nE + 255) / 256, 256>>>(row, nE, cnt);
    scan1_kernel<<<nb, SCAN_B>>>(cnt, partials, M);
    scan2_kernel<<<1, 256>>>(partials, nb, row_start, M);
    scan3_kernel<<<nb, SCAN_B>>>(cnt, partials, row_start, row_next, M);
    scatter_kernel<<<(nE + 255) / 256, 256>>>(row, col, vals, nE, row_next, scol, sval);

    // --- layer 1 ---
    const int gemm_blocks = (M + 127) / 128;
    gemm_bias_kernel<256, false><<<gemm_blocks, 256>>>(X, W1, b1, H, M);
    spmm_csr_kernel<<<(M + 7) / 8, 256>>>(row_start, scol, sval, H, S1, M);

    // --- layer 2 ---
    gemm_bias_kernel<128, true><<<gemm_blocks, 256>>>(S1, W2, b2, H, M);
    spmm_csr_kernel<<<(M + 7) / 8, 256>>>(row_start, scol, sval, H, out, M);
}

// round 3
// speedup vs baseline: 1.5604x; 1.0341x over previous
#include <cuda_runtime.h>
#include <cstdint>

// ---------------------------------------------------------------------------
// GCN: out = SpMM(relu(SpMM(X@W1+b1)) @ W2 + b2)
// R3: sort-chain overlapped with GEMM1 on a second captured stream,
//     double-buffered SGEMM, packed int2 edges + 4-deep unrolled CSR SpMM.
// ---------------------------------------------------------------------------

#define MAX_NODES 100000
#define MAX_EDGES 1600000
#define FEAT 128
#define SCAN_B 512
#define SCAN_NB ((MAX_NODES + SCAN_B - 1) / SCAN_B)   // 196

// Scratch
__device__ float g_H [(size_t)MAX_NODES * FEAT];   // GEMM output (reused)
__device__ float g_S1[(size_t)MAX_NODES * FEAT];   // SpMM1 output (pre-relu)
__device__ int   g_cnt[MAX_NODES];
__device__ int   g_row_start[MAX_NODES + 1];
__device__ int   g_row_next[MAX_NODES];
__device__ int   g_partials[SCAN_NB];
__device__ int2  g_edge[MAX_EDGES];                // {col, float_as_int(val)}

// ---------------------------------------------------------------------------
// CSR build: zero -> histogram -> 3-phase exclusive scan -> scatter.
// ---------------------------------------------------------------------------
__global__ void zero_cnt_kernel(int* __restrict__ cnt, int n)
{
    int i = blockIdx.x * blockDim.x + threadIdx.x;
    if (i < n) cnt[i] = 0;
}

__global__ void hist_kernel(const int* __restrict__ row, int nE, int* __restrict__ cnt)
{
    int i = blockIdx.x * blockDim.x + threadIdx.x;
    if (i < nE) atomicAdd(&cnt[row[i]], 1);
}

__global__ void scan1_kernel(const int* __restrict__ cnt, int* __restrict__ partials, int n)
{
    __shared__ int sh[SCAN_B];
    int i = blockIdx.x * SCAN_B + threadIdx.x;
    sh[threadIdx.x] = (i < n) ? cnt[i] : 0;
    __syncthreads();
#pragma unroll
    for (int off = SCAN_B / 2; off > 0; off >>= 1) {
        if (threadIdx.x < off) sh[threadIdx.x] += sh[threadIdx.x + off];
        __syncthreads();
    }
    if (threadIdx.x == 0) partials[blockIdx.x] = sh[0];
}

__global__ void scan2_kernel(int* __restrict__ partials, int nb,
                             int* __restrict__ row_start, int n)
{
    __shared__ int sh[256];
    int tid = threadIdx.x;
    int v = (tid < nb) ? partials[tid] : 0;
    sh[tid] = v;
    __syncthreads();
#pragma unroll
    for (int off = 1; off < 256; off <<= 1) {
        int t = (tid >= off) ? sh[tid - off] : 0;
        __syncthreads();
        sh[tid] += t;
        __syncthreads();
    }
    if (tid < nb) partials[tid] = sh[tid] - v;        // exclusive
    if (tid == 255) row_start[n] = sh[255];           // grand total
}

__global__ void scan3_kernel(const int* __restrict__ cnt, const int* __restrict__ partials,
                             int* __restrict__ row_start, int* __restrict__ row_next, int n)
{
    __shared__ int sh[SCAN_B];
    int tid = threadIdx.x;
    int i = blockIdx.x * SCAN_B + tid;
    int v = (i < n) ? cnt[i] : 0;
    sh[tid] = v;
    __syncthreads();
#pragma unroll
    for (int off = 1; off < SCAN_B; off <<= 1) {
        int t = (tid >= off) ? sh[tid - off] : 0;
        __syncthreads();
        sh[tid] += t;
        __syncthreads();
    }
    if (i < n) {
        int excl = sh[tid] - v + partials[blockIdx.x];
        row_start[i] = excl;
        row_next[i]  = excl;
    }
}

__global__ void scatter_kernel(const int* __restrict__ row, const int* __restrict__ col,
                               const float* __restrict__ vals, int nE,
                               int* __restrict__ row_next, int2* __restrict__ edge)
{
    int i = blockIdx.x * blockDim.x + threadIdx.x;
    if (i < nE) {
        int r = row[i];
        int p = atomicAdd(&row_next[r], 1);
        edge[p] = make_int2(col[i], __float_as_int(vals[i]));   // single 8B store
    }
}

// ---------------------------------------------------------------------------
// Double-buffered register-blocked SGEMM + bias (+ReLU on A):
//   C[M,128] = act(A)[M,K] @ W[K,128] + b
// BM=128, BK=16; 256 threads, 8x8 acc/thread; 2-deep smem ping-pong.
// ---------------------------------------------------------------------------
template <int K, bool RELU>
__global__ __launch_bounds__(256, 2) void gemm_bias_kernel(
    const float* __restrict__ A, const float* __restrict__ W,
    const float* __restrict__ bias, float* __restrict__ C, int M)
{
    constexpr int BM = 128, BK = 16, N = 128;
    constexpr int T = K / BK;
    __shared__ float As[2][BK][BM + 4];
    __shared__ float Ws[2][BK][N];

    const int tid = threadIdx.x;
    const int tn  = tid & 15;
    const int tm  = tid >> 4;
    const int m0  = blockIdx.x * BM;

    // per-thread load coords (A tile: 512 float4; W tile: 512 float4)
    const int a_rr0 = tid >> 2,            a_cc0 = (tid & 3) << 2;
    const int a_rr1 = (tid + 256) >> 2,    a_cc1 = ((tid + 256) & 3) << 2;
    const int w_rr0 = tid >> 5,            w_cc0 = (tid & 31) << 2;
    const int w_rr1 = (tid + 256) >> 5,    w_cc1 = w_cc0;

    float4 ra0, ra1, rw0, rw1;

    auto ld_tile = [&](int t) {
        int k0 = t * BK;
        int g0 = m0 + a_rr0, g1 = m0 + a_rr1;
        ra0 = make_float4(0.f, 0.f, 0.f, 0.f);
        ra1 = make_float4(0.f, 0.f, 0.f, 0.f);
        if (g0 < M) ra0 = *(const float4*)(A + (size_t)g0 * K + k0 + a_cc0);
        if (g1 < M) ra1 = *(const float4*)(A + (size_t)g1 * K + k0 + a_cc1);
        if (RELU) {
            ra0.x = fmaxf(ra0.x, 0.f); ra0.y = fmaxf(ra0.y, 0.f);
            ra0.z = fmaxf(ra0.z, 0.f); ra0.w = fmaxf(ra0.w, 0.f);
            ra1.x = fmaxf(ra1.x, 0.f); ra1.y = fmaxf(ra1.y, 0.f);
            ra1.z = fmaxf(ra1.z, 0.f); ra1.w = fmaxf(ra1.w, 0.f);
        }
        rw0 = *(const float4*)(W + (size_t)(k0 + w_rr0) * N + w_cc0);
        rw1 = *(const float4*)(W + (size_t)(k0 + w_rr1) * N + w_cc1);
    };
    auto st_tile = [&](int b) {
        As[b][a_cc0 + 0][a_rr0] = ra0.x;  As[b][a_cc0 + 1][a_rr0] = ra0.y;
        As[b][a_cc0 + 2][a_rr0] = ra0.z;  As[b][a_cc0 + 3][a_rr0] = ra0.w;
        As[b][a_cc1 + 0][a_rr1] = ra1.x;  As[b][a_cc1 + 1][a_rr1] = ra1.y;
        As[b][a_cc1 + 2][a_rr1] = ra1.z;  As[b][a_cc1 + 3][a_rr1] = ra1.w;
        *(float4*)(&Ws[b][w_rr0][w_cc0]) = rw0;
        *(float4*)(&Ws[b][w_rr1][w_cc1]) = rw1;
    };

    float acc[8][8];
#pragma unroll
    for (int i = 0; i < 8; i++)
#pragma unroll
        for (int j = 0; j < 8; j++) acc[i][j] = 0.f;

    ld_tile(0);
    st_tile(0);
    __syncthreads();

    for (int t = 0; t < T; t++) {
        if (t + 1 < T) ld_tile(t + 1);
        const int b = t & 1;
#pragma unroll
        for (int kk = 0; kk < BK; kk++) {
            float a[8], w[8];
            *(float4*)&a[0] = *(const float4*)(&As[b][kk][tm * 8]);
            *(float4*)&a[4] = *(const float4*)(&As[b][kk][tm * 8 + 4]);
            *(float4*)&w[0] = *(const float4*)(&Ws[b][kk][tn * 8]);
            *(float4*)&w[4] = *(const float4*)(&Ws[b][kk][tn * 8 + 4]);
#pragma unroll
            for (int i = 0; i < 8; i++)
#pragma unroll
                for (int j = 0; j < 8; j++)
                    acc[i][j] += a[i] * w[j];
        }
        if (t + 1 < T) {
            st_tile((t + 1) & 1);
            __syncthreads();
        }
    }

    float bb[8];
    *(float4*)&bb[0] = *(const float4*)(bias + tn * 8);
    *(float4*)&bb[4] = *(const float4*)(bias + tn * 8 + 4);
#pragma unroll
    for (int i = 0; i < 8; i++) {
        int gr = m0 + tm * 8 + i;
        if (gr < M) {
            float4 o0 = make_float4(acc[i][0] + bb[0], acc[i][1] + bb[1],
                                    acc[i][2] + bb[2], acc[i][3] + bb[3]);
            float4 o1 = make_float4(acc[i][4] + bb[4], acc[i][5] + bb[5],
                                    acc[i][6] + bb[6], acc[i][7] + bb[7]);
            float* cp = C + (size_t)gr * N + tn * 8;
            *(float4*)(cp)     = o0;
            *(float4*)(cp + 4) = o1;
        }
    }
}

// ---------------------------------------------------------------------------
// CSR SpMM, atomic-free: warp per row, lane l owns floats [4l,4l+3].
// 4-deep unroll for gather MLP; packed int2 edge list (uniform 8B broadcast).
// ---------------------------------------------------------------------------
__global__ __launch_bounds__(256) void spmm_csr_kernel(
    const int* __restrict__ row_start, const int2* __restrict__ edge,
    const float* __restrict__ H, float* __restrict__ out, int n)
{
    int r    = blockIdx.x * 8 + (threadIdx.x >> 5);
    int lane = threadIdx.x & 31;
    if (r >= n) return;

    int s = row_start[r];
    int e = row_start[r + 1];

    float4 acc = make_float4(0.f, 0.f, 0.f, 0.f);
    const int fo = lane << 2;
    int i = s;
    for (; i + 4 <= e; i += 4) {
        int2 e0 = edge[i], e1 = edge[i + 1], e2 = edge[i + 2], e3 = edge[i + 3];
        float4 h0 = *(const float4*)(H + (size_t)e0.x * FEAT + fo);
        float4 h1 = *(const float4*)(H + (size_t)e1.x * FEAT + fo);
        float4 h2 = *(const float4*)(H + (size_t)e2.x * FEAT + fo);
        float4 h3 = *(const float4*)(H + (size_t)e3.x * FEAT + fo);
        float v0 = __int_as_float(e0.y), v1 = __int_as_float(e1.y);
        float v2 = __int_as_float(e2.y), v3 = __int_as_float(e3.y);
        acc.x += v0 * h0.x + v1 * h1.x + v2 * h2.x + v3 * h3.x;
        acc.y += v0 * h0.y + v1 * h1.y + v2 * h2.y + v3 * h3.y;
        acc.z += v0 * h0.z + v1 * h1.z + v2 * h2.z + v3 * h3.z;
        acc.w += v0 * h0.w + v1 * h1.w + v2 * h2.w + v3 * h3.w;
    }
    for (; i < e; i++) {
        int2 ev = edge[i];
        float v = __int_as_float(ev.y);
        float4 h = *(const float4*)(H + (size_t)ev.x * FEAT + fo);
        acc.x += v * h.x; acc.y += v * h.y; acc.z += v * h.z; acc.w += v * h.w;
    }
    *(float4*)(out + (size_t)r * FEAT + fo) = acc;
}

// ---------------------------------------------------------------------------
extern "C" void kernel_launch(void* const* d_in, const int* in_sizes, int n_in,
                              void* d_out, int out_size)
{
    const float* X    = (const float*)d_in[0];
    const float* W1   = (const float*)d_in[1];
    const float* b1   = (const float*)d_in[2];
    const float* W2   = (const float*)d_in[3];
    const float* b2   = (const float*)d_in[4];
    const float* vals = (const float*)d_in[5];
    const int*   row  = (const int*)d_in[6];
    const int*   col  = (const int*)d_in[7];

    const int M  = in_sizes[0] / 256;   // 100000
    const int nE = in_sizes[5];         // 1600000

    float *H, *S1;
    int *cnt, *row_start, *row_next, *partials;
    int2 *edge;
    cudaGetSymbolAddress((void**)&H,         g_H);
    cudaGetSymbolAddress((void**)&S1,        g_S1);
    cudaGetSymbolAddress((void**)&cnt,       g_cnt);
    cudaGetSymbolAddress((void**)&row_start, g_row_start);
    cudaGetSymbolAddress((void**)&row_next,  g_row_next);
    cudaGetSymbolAddress((void**)&partials,  g_partials);
    cudaGetSymbolAddress((void**)&edge,      g_edge);
    float* out = (float*)d_out;

    // Side stream + fork/join events (created once, outside capture; the
    // event-fork pattern below is graph-capture legal and reproduced
    // identically on every call).
    static cudaStream_t s_side = nullptr;
    static cudaEvent_t  ev_fork = nullptr, ev_join = nullptr;
    if (s_side == nullptr) {
        cudaStreamCreateWithFlags(&s_side, cudaStreamNonBlocking);
        cudaEventCreateWithFlags(&ev_fork, cudaEventDisableTiming);
        cudaEventCreateWithFlags(&ev_join, cudaEventDisableTiming);
    }

    const int nb = (M + SCAN_B - 1) / SCAN_B;   // 196

    // Fork: CSR build on side stream, concurrent with GEMM1 on main stream.
    cudaEventRecord(ev_fork, 0);
    cudaStreamWaitEvent(s_side, ev_fork, 0);

    zero_cnt_kernel<<<(M + 255) / 256, 256, 0, s_side>>>(cnt, M);
    hist_kernel<<<(nE + 255) / 256, 256, 0, s_side>>>(row, nE, cnt);
    scan1_kernel<<<nb, SCAN_B, 0, s_side>>>(cnt, partials, M);
    scan2_kernel<<<1, 256, 0, s_side>>>(partials, nb, row_start, M);
    scan3_kernel<<<nb, SCAN_B, 0, s_side>>>(cnt, partials, row_start, row_next, M);
    scatter_kernel<<<(nE + 255) / 256, 256, 0, s_side>>>(row, col, vals, nE, row_next, edge);
    cudaEventRecord(ev_join, s_side);

    // Main stream: GEMM1 (independent of the CSR build).
    const int gemm_blocks = (M + 127) / 128;
    gemm_bias_kernel<256, false><<<gemm_blocks, 256>>>(X, W1, b1, H, M);

    // Join, then the dependent chain.
    cudaStreamWaitEvent(0, ev_join, 0);
    spmm_csr_kernel<<<(M + 7) / 8, 256>>>(row_start, edge, H, S1, M);
    gemm_bias_kernel<128, true><<<gemm_blocks, 256>>>(S1, W2, b2, H, M);
    spmm_csr_kernel<<<(M + 7) / 8, 256>>>(row_start, edge, H, out, M);
}

// round 4
// speedup vs baseline: 3.2064x; 2.0549x over previous
#include <cuda_runtime.h>
#include <cuda_fp16.h>
#include <cstdint>

// ---------------------------------------------------------------------------
// GCN: out = SpMM(relu(SpMM(X@W1+b1)) @ W2 + b2)
// R4: fp16 HMMA (mma.sync.m16n8k16, fp32 accum) GEMMs; fp16 H tables so the
//     L2-bound SpMM gather moves half the bytes; CSR build overlapped on a
//     side stream. Accumulations and final output stay fp32.
// ---------------------------------------------------------------------------

#define MAX_NODES 100000
#define MAX_EDGES 1600000
#define FEAT 128
#define SCAN_B 512
#define SCAN_NB ((MAX_NODES + SCAN_B - 1) / SCAN_B)

// Scratch
__device__ __align__(16) __half g_H [(size_t)MAX_NODES * FEAT];  // GEMM out (fp16)
__device__ __align__(16) __half g_S1[(size_t)MAX_NODES * FEAT];  // relu(SpMM1) (fp16)
__device__ int  g_cnt[MAX_NODES];
__device__ int  g_row_start[MAX_NODES + 1];
__device__ int  g_row_next[MAX_NODES];
__device__ int  g_partials[SCAN_NB];
__device__ int2 g_edge[MAX_EDGES];                 // {col, float_as_int(val)}

// ---------------------------------------------------------------------------
// CSR build
// ---------------------------------------------------------------------------
__global__ void zero_cnt_kernel(int* __restrict__ cnt, int n)
{
    int i = blockIdx.x * blockDim.x + threadIdx.x;
    if (i < n) cnt[i] = 0;
}

__global__ void hist_kernel(const int* __restrict__ row, int nE, int* __restrict__ cnt)
{
    int i = blockIdx.x * blockDim.x + threadIdx.x;
    if (i < nE) atomicAdd(&cnt[row[i]], 1);
}

__global__ void scan1_kernel(const int* __restrict__ cnt, int* __restrict__ partials, int n)
{
    __shared__ int sh[SCAN_B];
    int i = blockIdx.x * SCAN_B + threadIdx.x;
    sh[threadIdx.x] = (i < n) ? cnt[i] : 0;
    __syncthreads();
#pragma unroll
    for (int off = SCAN_B / 2; off > 0; off >>= 1) {
        if (threadIdx.x < off) sh[threadIdx.x] += sh[threadIdx.x + off];
        __syncthreads();
    }
    if (threadIdx.x == 0) partials[blockIdx.x] = sh[0];
}

__global__ void scan2_kernel(int* __restrict__ partials, int nb,
                             int* __restrict__ row_start, int n)
{
    __shared__ int sh[256];
    int tid = threadIdx.x;
    int v = (tid < nb) ? partials[tid] : 0;
    sh[tid] = v;
    __syncthreads();
#pragma unroll
    for (int off = 1; off < 256; off <<= 1) {
        int t = (tid >= off) ? sh[tid - off] : 0;
        __syncthreads();
        sh[tid] += t;
        __syncthreads();
    }
    if (tid < nb) partials[tid] = sh[tid] - v;
    if (tid == 255) row_start[n] = sh[255];
}

__global__ void scan3_kernel(const int* __restrict__ cnt, const int* __restrict__ partials,
                             int* __restrict__ row_start, int* __restrict__ row_next, int n)
{
    __shared__ int sh[SCAN_B];
    int tid = threadIdx.x;
    int i = blockIdx.x * SCAN_B + tid;
    int v = (i < n) ? cnt[i] : 0;
    sh[tid] = v;
    __syncthreads();
#pragma unroll
    for (int off = 1; off < SCAN_B; off <<= 1) {
        int t = (tid >= off) ? sh[tid - off] : 0;
        __syncthreads();
        sh[tid] += t;
        __syncthreads();
    }
    if (i < n) {
        int excl = sh[tid] - v + partials[blockIdx.x];
        row_start[i] = excl;
        row_next[i]  = excl;
    }
}

__global__ void scatter_kernel(const int* __restrict__ row, const int* __restrict__ col,
                               const float* __restrict__ vals, int nE,
                               int* __restrict__ row_next, int2* __restrict__ edge)
{
    int i = blockIdx.x * blockDim.x + threadIdx.x;
    if (i < nE) {
        int r = row[i];
        int p = atomicAdd(&row_next[r], 1);
        edge[p] = make_int2(col[i], __float_as_int(vals[i]));
    }
}

// ---------------------------------------------------------------------------
// HMMA GEMM: C_h[M,128] = (A[M,K] @ W[K,128] + bias) in fp16 out, fp32 accum.
// 256 threads = 8 warps (4x2). BM=128, BN=128, BK=32. Warp tile 32x64.
// A_HALF selects fp16 A source (GEMM2) vs fp32 A converted at staging (GEMM1).
// ---------------------------------------------------------------------------
__device__ __forceinline__ void mma16816(float* d, const uint32_t* a, const uint32_t* b)
{
    asm volatile(
        "mma.sync.aligned.m16n8k16.row.col.f32.f16.f16.f32 "
        "{%0,%1,%2,%3}, {%4,%5,%6,%7}, {%8,%9}, {%0,%1,%2,%3};\n"
        : "+f"(d[0]), "+f"(d[1]), "+f"(d[2]), "+f"(d[3])
        : "r"(a[0]), "r"(a[1]), "r"(a[2]), "r"(a[3]), "r"(b[0]), "r"(b[1]));
}

__device__ __forceinline__ void ldsm_x4(uint32_t* r, uint32_t addr)
{
    asm volatile("ldmatrix.sync.aligned.m8n8.x4.shared.b16 {%0,%1,%2,%3}, [%4];"
                 : "=r"(r[0]), "=r"(r[1]), "=r"(r[2]), "=r"(r[3]) : "r"(addr));
}

__device__ __forceinline__ void ldsm_x4_t(uint32_t* r, uint32_t addr)
{
    asm volatile("ldmatrix.sync.aligned.m8n8.x4.trans.shared.b16 {%0,%1,%2,%3}, [%4];"
                 : "=r"(r[0]), "=r"(r[1]), "=r"(r[2]), "=r"(r[3]) : "r"(addr));
}

#define AS_STRIDE 56   // halves; 112B rows: 16B-aligned, ldmatrix conflict-free
#define WS_STRIDE 136  // halves; 272B rows: 16B-aligned, ldmatrix conflict-free

template <int K, bool A_HALF>
__global__ __launch_bounds__(256) void gemm_hmma_kernel(
    const void* __restrict__ A_, const float* __restrict__ W,
    const float* __restrict__ bias, __half* __restrict__ C, int M)
{
    constexpr int BM = 128, BK = 32, N = 128;
    constexpr int T = K / BK;
    __shared__ __half As[BM * AS_STRIDE];
    __shared__ __half Ws[BK * WS_STRIDE];

    const int tid  = threadIdx.x;
    const int lane = tid & 31;
    const int wid  = tid >> 5;
    const int wm   = wid >> 1;       // 0..3
    const int wn   = wid & 1;        // 0..1
    const int m0   = blockIdx.x * BM;

    float acc[2][8][4];
#pragma unroll
    for (int i = 0; i < 2; i++)
#pragma unroll
        for (int j = 0; j < 8; j++)
#pragma unroll
            for (int q = 0; q < 4; q++) acc[i][j][q] = 0.f;

    const uint32_t sAs = (uint32_t)__cvta_generic_to_shared(As);
    const uint32_t sWs = (uint32_t)__cvta_generic_to_shared(Ws);

    for (int t = 0; t < T; t++) {
        const int k0 = t * BK;
        // ---- stage A tile [128 x 32] ----
        if (A_HALF) {
            const __half* A = (const __half*)A_;
            // 512 uint4 (8 halves each): 2 per thread
#pragma unroll
            for (int i = 0; i < 2; i++) {
                int idx = tid + i * 256;
                int rr = idx >> 2, cc = (idx & 3) << 3;
                int gr = m0 + rr;
                uint4 v = make_uint4(0, 0, 0, 0);
                if (gr < M)
                    v = *(const uint4*)(A + (size_t)gr * K + k0 + cc);
                *(uint4*)(&As[rr * AS_STRIDE + cc]) = v;
            }
        } else {
            const float* A = (const float*)A_;
            // 1024 float4: 4 per thread, converted to fp16
#pragma unroll
            for (int i = 0; i < 4; i++) {
                int idx = tid + i * 256;
                int rr = idx >> 3, cc = (idx & 7) << 2;
                int gr = m0 + rr;
                float4 v = make_float4(0.f, 0.f, 0.f, 0.f);
                if (gr < M)
                    v = *(const float4*)(A + (size_t)gr * K + k0 + cc);
                __half2* dst = (__half2*)(&As[rr * AS_STRIDE + cc]);
                dst[0] = __floats2half2_rn(v.x, v.y);
                dst[1] = __floats2half2_rn(v.z, v.w);
            }
        }
        // ---- stage W tile [32 x 128] (fp32 -> fp16) ----
#pragma unroll
        for (int i = 0; i < 4; i++) {
            int idx = tid + i * 256;
            int rr = idx >> 5, cc = (idx & 31) << 2;
            float4 v = *(const float4*)(W + (size_t)(k0 + rr) * N + cc);
            __half2* dst = (__half2*)(&Ws[rr * WS_STRIDE + cc]);
            dst[0] = __floats2half2_rn(v.x, v.y);
            dst[1] = __floats2half2_rn(v.z, v.w);
        }
        __syncthreads();

        // ---- compute: 2 k16 steps ----
#pragma unroll
        for (int ks = 0; ks < 2; ks++) {
            const int kk = ks * 16;
            uint32_t a[2][4], b[4][4];
#pragma unroll
            for (int mi = 0; mi < 2; mi++) {
                int r0 = wm * 32 + mi * 16;
                uint32_t addr = sAs + ((r0 + (lane & 15)) * AS_STRIDE
                                       + kk + ((lane >> 4) << 3)) * 2;
                ldsm_x4(a[mi], addr);
            }
#pragma unroll
            for (int p = 0; p < 4; p++) {
                int c0 = wn * 64 + p * 16;
                uint32_t addr = sWs + ((kk + (lane & 15)) * WS_STRIDE
                                       + c0 + ((lane >> 4) << 3)) * 2;
                ldsm_x4_t(b[p], addr);
            }
#pragma unroll
            for (int mi = 0; mi < 2; mi++)
#pragma unroll
                for (int p = 0; p < 4; p++) {
                    mma16816(acc[mi][2 * p],     a[mi], &b[p][0]);
                    mma16816(acc[mi][2 * p + 1], a[mi], &b[p][2]);
                }
        }
        __syncthreads();
    }

    // ---- epilogue: +bias, fp16 store ----
    const int rq = lane >> 2;            // 0..7
    const int cq = (lane & 3) << 1;      // 0,2,4,6
#pragma unroll
    for (int ni = 0; ni < 8; ni++) {
        int gc = wn * 64 + ni * 8 + cq;
        float2 bb = *(const float2*)(bias + gc);
#pragma unroll
        for (int mi = 0; mi < 2; mi++) {
            int r_base = m0 + wm * 32 + mi * 16 + rq;
            float* d = acc[mi][ni];
            if (r_base < M)
                *(__half2*)(C + (size_t)r_base * N + gc) =
                    __floats2half2_rn(d[0] + bb.x, d[1] + bb.y);
            if (r_base + 8 < M)
                *(__half2*)(C + (size_t)(r_base + 8) * N + gc) =
                    __floats2half2_rn(d[2] + bb.x, d[3] + bb.y);
        }
    }
}

// ---------------------------------------------------------------------------
// CSR SpMM over fp16 H: warp per row, lane l owns features [4l..4l+3].
// OUT_HALF_RELU: store relu(acc) as fp16 (layer 1); else store fp32 (layer 2).
// ---------------------------------------------------------------------------
template <bool OUT_HALF_RELU>
__global__ __launch_bounds__(256) void spmm_csr_kernel(
    const int* __restrict__ row_start, const int2* __restrict__ edge,
    const __half* __restrict__ H, void* __restrict__ out_, int n)
{
    int r    = blockIdx.x * 8 + (threadIdx.x >> 5);
    int lane = threadIdx.x & 31;
    if (r >= n) return;

    int s = row_start[r];
    int e = row_start[r + 1];

    float4 acc = make_float4(0.f, 0.f, 0.f, 0.f);
    const int fo = lane << 2;           // feature offset (4 halves = 8B)

    auto fma_edge = [&](int2 ev) {
        float v = __int_as_float(ev.y);
        uint2 u = *(const uint2*)(H + (size_t)ev.x * FEAT + fo);
        float2 h01 = __half22float2(*(const __half2*)&u.x);
        float2 h23 = __half22float2(*(const __half2*)&u.y);
        acc.x += v * h01.x; acc.y += v * h01.y;
        acc.z += v * h23.x; acc.w += v * h23.y;
    };

    int i = s;
    for (; i + 4 <= e; i += 4) {
        int2 e0 = edge[i], e1 = edge[i + 1], e2 = edge[i + 2], e3 = edge[i + 3];
        fma_edge(e0); fma_edge(e1); fma_edge(e2); fma_edge(e3);
    }
    for (; i < e; i++) fma_edge(edge[i]);

    if (OUT_HALF_RELU) {
        __half* out = (__half*)out_;
        uint2 o;
        *(__half2*)&o.x = __floats2half2_rn(fmaxf(acc.x, 0.f), fmaxf(acc.y, 0.f));
        *(__half2*)&o.y = __floats2half2_rn(fmaxf(acc.z, 0.f), fmaxf(acc.w, 0.f));
        *(uint2*)(out + (size_t)r * FEAT + fo) = o;
    } else {
        float* out = (float*)out_;
        *(float4*)(out + (size_t)r * FEAT + fo) = acc;
    }
}

// ---------------------------------------------------------------------------
extern "C" void kernel_launch(void* const* d_in, const int* in_sizes, int n_in,
                              void* d_out, int out_size)
{
    const float* X    = (const float*)d_in[0];
    const float* W1   = (const float*)d_in[1];
    const float* b1   = (const float*)d_in[2];
    const float* W2   = (const float*)d_in[3];
    const float* b2   = (const float*)d_in[4];
    const float* vals = (const float*)d_in[5];
    const int*   row  = (const int*)d_in[6];
    const int*   col  = (const int*)d_in[7];

    const int M  = in_sizes[0] / 256;   // 100000
    const int nE = in_sizes[5];         // 1600000

    __half *H, *S1;
    int *cnt, *row_start, *row_next, *partials;
    int2 *edge;
    cudaGetSymbolAddress((void**)&H,         g_H);
    cudaGetSymbolAddress((void**)&S1,        g_S1);
    cudaGetSymbolAddress((void**)&cnt,       g_cnt);
    cudaGetSymbolAddress((void**)&row_start, g_row_start);
    cudaGetSymbolAddress((void**)&row_next,  g_row_next);
    cudaGetSymbolAddress((void**)&partials,  g_partials);
    cudaGetSymbolAddress((void**)&edge,      g_edge);
    float* out = (float*)d_out;

    static cudaStream_t s_side = nullptr;
    static cudaEvent_t  ev_fork = nullptr, ev_join = nullptr;
    if (s_side == nullptr) {
        cudaStreamCreateWithFlags(&s_side, cudaStreamNonBlocking);
        cudaEventCreateWithFlags(&ev_fork, cudaEventDisableTiming);
        cudaEventCreateWithFlags(&ev_join, cudaEventDisableTiming);
    }

    const int nb = (M + SCAN_B - 1) / SCAN_B;

    // Fork: CSR build on side stream, concurrent with GEMM1.
    cudaEventRecord(ev_fork, 0);
    cudaStreamWaitEvent(s_side, ev_fork, 0);

    zero_cnt_kernel<<<(M + 511) / 512, 512, 0, s_side>>>(cnt, M);
    hist_kernel<<<(nE + 511) / 512, 512, 0, s_side>>>(row, nE, cnt);
    scan1_kernel<<<nb, SCAN_B, 0, s_side>>>(cnt, partials, M);
    scan2_kernel<<<1, 256, 0, s_side>>>(partials, nb, row_start, M);
    scan3_kernel<<<nb, SCAN_B, 0, s_side>>>(cnt, partials, row_start, row_next, M);
    scatter_kernel<<<(nE + 511) / 512, 512, 0, s_side>>>(row, col, vals, nE, row_next, edge);
    cudaEventRecord(ev_join, s_side);

    // Main stream: GEMM1 (X fp32 -> H fp16).
    const int gemm_blocks = (M + 127) / 128;
    gemm_hmma_kernel<256, false><<<gemm_blocks, 256>>>(X, W1, b1, H, M);

    cudaStreamWaitEvent(0, ev_join, 0);
    spmm_csr_kernel<true><<<(M + 7) / 8, 256>>>(row_start, edge, H, S1, M);   // -> relu fp16
    gemm_hmma_kernel<128, true><<<gemm_blocks, 256>>>(S1, W2, b2, H, M);      // -> H2 fp16
    spmm_csr_kernel<false><<<(M + 7) / 8, 256>>>(row_start, edge, H, out, M); // -> fp32 out
}